// round 1
// baseline (speedup 1.0000x reference)
#include <cuda_runtime.h>
#include <cuda_bf16.h>

#define N_NODES   100000
#define N_EDGES   1200000
#define NUM_GRAPHS 128
#define IN_DIM    5
#define HIDDEN    64

// -------- scratch (device globals; no allocations allowed) --------
__device__ __align__(16) float g_agg1[N_NODES * IN_DIM];     // 2.0 MB
__device__ __align__(16) float g_h1  [N_NODES * HIDDEN];     // 25.6 MB
__device__ __align__(16) float g_agg2[N_NODES * HIDDEN];     // 25.6 MB
__device__ __align__(16) float g_pool[NUM_GRAPHS * HIDDEN];  // add-pool
__device__              float g_cnt [NUM_GRAPHS];

// -------- K0: zero scratch --------
__global__ void k_zero() {
    int i = blockIdx.x * blockDim.x + threadIdx.x;
    int total = N_NODES * HIDDEN;          // g_agg2
    if (i < total) g_agg2[i] = 0.f;
    if (i < N_NODES * IN_DIM) g_agg1[i] = 0.f;
    if (i < NUM_GRAPHS * HIDDEN) g_pool[i] = 0.f;
    if (i < NUM_GRAPHS) g_cnt[i] = 0.f;
}

// -------- K1: layer-1 edge scatter: agg1[dst] += x[src] (IN_DIM=5) --------
__global__ void k_edge1(const float* __restrict__ x,
                        const int* __restrict__ src,
                        const int* __restrict__ dst) {
    int e = blockIdx.x * blockDim.x + threadIdx.x;
    if (e >= N_EDGES) return;
    int s = src[e], d = dst[e];
    #pragma unroll
    for (int k = 0; k < IN_DIM; k++)
        atomicAdd(&g_agg1[d * IN_DIM + k], x[s * IN_DIM + k]);
}

// -------- K2: layer-1 node update: h1 = relu(agg1@Wr + b + x@Wroot) --------
// block = 256 threads = 4 nodes x 64 output cols
__global__ void k_node1(const float* __restrict__ x,
                        const float* __restrict__ w_rel,   // [5,64]
                        const float* __restrict__ b_rel,   // [64]
                        const float* __restrict__ w_root)  // [5,64]
{
    __shared__ float swr[IN_DIM * HIDDEN];
    __shared__ float swo[IN_DIM * HIDDEN];
    __shared__ float sb[HIDDEN];
    int t = threadIdx.x;
    for (int i = t; i < IN_DIM * HIDDEN; i += blockDim.x) {
        swr[i] = w_rel[i];
        swo[i] = w_root[i];
    }
    if (t < HIDDEN) sb[t] = b_rel[t];
    __syncthreads();

    int j = t & 63;
    int local = t >> 6;
    int node = blockIdx.x * 4 + local;
    if (node >= N_NODES) return;

    float acc = sb[j];
    #pragma unroll
    for (int k = 0; k < IN_DIM; k++) {
        float a = g_agg1[node * IN_DIM + k];
        float xv = x[node * IN_DIM + k];
        acc += a * swr[k * HIDDEN + j] + xv * swo[k * HIDDEN + j];
    }
    g_h1[node * HIDDEN + j] = fmaxf(acc, 0.f);
}

// -------- K3: layer-2 edge scatter: agg2[dst] += h1[src] (64 floats) --------
// 16 threads per edge, each handles a float4 chunk, vector RED into L2.
__global__ void k_edge2(const int* __restrict__ src,
                        const int* __restrict__ dst) {
    int idx = blockIdx.x * blockDim.x + threadIdx.x;   // E*16 = 19.2M
    int e = idx >> 4;
    if (e >= N_EDGES) return;
    int c = (idx & 15) << 2;
    int s = src[e], d = dst[e];
    const float4 v = *reinterpret_cast<const float4*>(&g_h1[s * HIDDEN + c]);
    float* p = &g_agg2[d * HIDDEN + c];
    asm volatile("red.global.add.v4.f32 [%0], {%1,%2,%3,%4};"
                 :: "l"(p), "f"(v.x), "f"(v.y), "f"(v.z), "f"(v.w)
                 : "memory");
}

// -------- K4: layer-2 node update fused with pooling --------
// h2 = relu(agg2@Wr2 + b2 + h1@Wroot2); pool[batch[n]] += h2; cnt[batch[n]] += 1
// block = 256 threads = 4 nodes x 64 cols; weights staged in smem (32KB)
__global__ void k_node2_pool(const int* __restrict__ batch,
                             const float* __restrict__ w_rel,   // [64,64]
                             const float* __restrict__ b_rel,   // [64]
                             const float* __restrict__ w_root)  // [64,64]
{
    __shared__ float swr[HIDDEN * HIDDEN];
    __shared__ float swo[HIDDEN * HIDDEN];
    __shared__ float sb[HIDDEN];
    __shared__ float sagg[4][HIDDEN];
    __shared__ float sh1[4][HIDDEN];

    int t = threadIdx.x;
    for (int i = t; i < HIDDEN * HIDDEN; i += blockDim.x) {
        swr[i] = w_rel[i];
        swo[i] = w_root[i];
    }
    if (t < HIDDEN) sb[t] = b_rel[t];

    int j = t & 63;
    int local = t >> 6;
    int node = blockIdx.x * 4 + local;
    bool valid = (node < N_NODES);
    if (valid) {
        sagg[local][j] = g_agg2[node * HIDDEN + j];
        sh1[local][j]  = g_h1[node * HIDDEN + j];
    }
    __syncthreads();
    if (!valid) return;

    float acc = sb[j];
    #pragma unroll 16
    for (int k = 0; k < HIDDEN; k++) {
        acc += sagg[local][k] * swr[k * HIDDEN + j]
             + sh1[local][k]  * swo[k * HIDDEN + j];
    }
    acc = fmaxf(acc, 0.f);

    int g = batch[node];
    atomicAdd(&g_pool[g * HIDDEN + j], acc);
    if (j == 0) atomicAdd(&g_cnt[g], 1.f);
}

// -------- K5: final MLP head, one block, thread = graph --------
__global__ void k_head(const float* __restrict__ w_h1,  // [128,64]
                       const float* __restrict__ b_h1,  // [64]
                       const float* __restrict__ w_h2,  // [64,1]
                       const float* __restrict__ b_h2,  // [1]
                       float* __restrict__ out)
{
    __shared__ float sw1[2 * HIDDEN * HIDDEN];  // 32KB
    __shared__ float sb1[HIDDEN];
    __shared__ float sw2[HIDDEN];
    int t = threadIdx.x;
    for (int i = t; i < 2 * HIDDEN * HIDDEN; i += blockDim.x) sw1[i] = w_h1[i];
    if (t < HIDDEN) { sb1[t] = b_h1[t]; sw2[t] = w_h2[t]; }
    __syncthreads();

    int g = t;
    if (g >= NUM_GRAPHS) return;

    float inv = 1.f / fmaxf(g_cnt[g], 1.f);

    float h[HIDDEN];
    #pragma unroll
    for (int j = 0; j < HIDDEN; j++) h[j] = sb1[j];

    // i in [0,64): mean-pool part; i in [64,128): add-pool part
    for (int i = 0; i < HIDDEN; i++) {
        float p = g_pool[g * HIDDEN + i];
        float gm = p * inv;   // mean
        float ga = p;         // add
        #pragma unroll 8
        for (int j = 0; j < HIDDEN; j++) {
            h[j] += gm * sw1[i * HIDDEN + j]
                  + ga * sw1[(HIDDEN + i) * HIDDEN + j];
        }
    }
    float o = b_h2[0];
    #pragma unroll
    for (int j = 0; j < HIDDEN; j++) o += fmaxf(h[j], 0.f) * sw2[j];
    out[g] = o;
}

extern "C" void kernel_launch(void* const* d_in, const int* in_sizes, int n_in,
                              void* d_out, int out_size) {
    const float* x       = (const float*)d_in[0];
    const int*   eidx    = (const int*)d_in[1];   // [2, E]
    const int*   batch   = (const int*)d_in[2];
    const float* w_rel1  = (const float*)d_in[3];
    const float* b_rel1  = (const float*)d_in[4];
    const float* w_root1 = (const float*)d_in[5];
    const float* w_rel2  = (const float*)d_in[6];
    const float* b_rel2  = (const float*)d_in[7];
    const float* w_root2 = (const float*)d_in[8];
    const float* w_h1    = (const float*)d_in[9];
    const float* b_h1    = (const float*)d_in[10];
    const float* w_h2    = (const float*)d_in[11];
    const float* b_h2    = (const float*)d_in[12];
    float* out = (float*)d_out;

    const int* src = eidx;
    const int* dst = eidx + N_EDGES;

    // K0: zero scratch
    {
        int total = N_NODES * HIDDEN;
        k_zero<<<(total + 255) / 256, 256>>>();
    }
    // K1: layer-1 edge scatter
    k_edge1<<<(N_EDGES + 255) / 256, 256>>>(x, src, dst);
    // K2: layer-1 node update
    k_node1<<<(N_NODES + 3) / 4, 256>>>(x, w_rel1, b_rel1, w_root1);
    // K3: layer-2 edge scatter (16 threads/edge)
    {
        long long threads = (long long)N_EDGES * 16;
        k_edge2<<<(int)((threads + 255) / 256), 256>>>(src, dst);
    }
    // K4: layer-2 node update + pooling
    k_node2_pool<<<(N_NODES + 3) / 4, 256>>>(batch, w_rel2, b_rel2, w_root2);
    // K5: head
    k_head<<<1, 128>>>(w_h1, b_h1, w_h2, b_h2, out);
}

// round 2
// speedup vs baseline: 1.3628x; 1.3628x over previous
#include <cuda_runtime.h>
#include <cuda_bf16.h>

#define N_NODES   100000
#define N_EDGES   1200000
#define NUM_GRAPHS 128
#define IN_DIM    5
#define HIDDEN    64

// -------- scratch (device globals; no allocations allowed) --------
__device__ __align__(16) float g_agg1[N_NODES * IN_DIM];     // 2.0 MB
__device__ __align__(16) float g_h1  [N_NODES * HIDDEN];     // 25.6 MB
__device__ __align__(16) float g_agg2[N_NODES * HIDDEN];     // 25.6 MB
__device__ __align__(16) float g_pool[NUM_GRAPHS * HIDDEN];  // add-pool
__device__              float g_cnt [NUM_GRAPHS];

// -------- K0: zero scratch --------
__global__ void k_zero() {
    int i = blockIdx.x * blockDim.x + threadIdx.x;
    int total = N_NODES * HIDDEN;          // g_agg2
    if (i < total) g_agg2[i] = 0.f;
    if (i < N_NODES * IN_DIM) g_agg1[i] = 0.f;
    if (i < NUM_GRAPHS * HIDDEN) g_pool[i] = 0.f;
    if (i < NUM_GRAPHS) g_cnt[i] = 0.f;
}

// -------- K1: layer-1 edge scatter: agg1[dst] += x[src] (IN_DIM=5) --------
__global__ void k_edge1(const float* __restrict__ x,
                        const int* __restrict__ src,
                        const int* __restrict__ dst) {
    int e = blockIdx.x * blockDim.x + threadIdx.x;
    if (e >= N_EDGES) return;
    int s = src[e], d = dst[e];
    #pragma unroll
    for (int k = 0; k < IN_DIM; k++)
        atomicAdd(&g_agg1[d * IN_DIM + k], x[s * IN_DIM + k]);
}

// -------- K2: layer-1 node update: h1 = relu(agg1@Wr + b + x@Wroot) --------
__global__ void k_node1(const float* __restrict__ x,
                        const float* __restrict__ w_rel,   // [5,64]
                        const float* __restrict__ b_rel,   // [64]
                        const float* __restrict__ w_root)  // [5,64]
{
    __shared__ float swr[IN_DIM * HIDDEN];
    __shared__ float swo[IN_DIM * HIDDEN];
    __shared__ float sb[HIDDEN];
    int t = threadIdx.x;
    for (int i = t; i < IN_DIM * HIDDEN; i += blockDim.x) {
        swr[i] = w_rel[i];
        swo[i] = w_root[i];
    }
    if (t < HIDDEN) sb[t] = b_rel[t];
    __syncthreads();

    int j = t & 63;
    int local = t >> 6;
    int node = blockIdx.x * 4 + local;
    if (node >= N_NODES) return;

    float acc = sb[j];
    #pragma unroll
    for (int k = 0; k < IN_DIM; k++) {
        float a = g_agg1[node * IN_DIM + k];
        float xv = x[node * IN_DIM + k];
        acc += a * swr[k * HIDDEN + j] + xv * swo[k * HIDDEN + j];
    }
    g_h1[node * HIDDEN + j] = fmaxf(acc, 0.f);
}

// -------- K3: layer-2 edge scatter: agg2[dst] += h1[src] (64 floats) --------
__global__ void k_edge2(const int* __restrict__ src,
                        const int* __restrict__ dst) {
    int idx = blockIdx.x * blockDim.x + threadIdx.x;   // E*16 = 19.2M
    int e = idx >> 4;
    if (e >= N_EDGES) return;
    int c = (idx & 15) << 2;
    int s = src[e], d = dst[e];
    const float4 v = *reinterpret_cast<const float4*>(&g_h1[s * HIDDEN + c]);
    float* p = &g_agg2[d * HIDDEN + c];
    asm volatile("red.global.add.v4.f32 [%0], {%1,%2,%3,%4};"
                 :: "l"(p), "f"(v.x), "f"(v.y), "f"(v.z), "f"(v.w)
                 : "memory");
}

// -------- K4: layer-2 node update (tiled GEMM) fused with pooling --------
// C[64 nodes x 64 cols] per block; 256 threads, 4x4 register microtile.
// K=128 handled as two 64-stages: stage0 = agg2 @ w_rel2, stage1 = h1 @ w_root2.
#define TM 64
#define SA_STRIDE 68                    // padded, 16B-aligned rows, reduces STS conflicts
#define SA_FLOATS (64 * SA_STRIDE)      // 4352
#define SB_FLOATS (64 * HIDDEN)         // 4096

__global__ __launch_bounds__(256, 2)
void k_node2_pool(const int* __restrict__ batch,
                  const float* __restrict__ w_rel,   // [64,64]
                  const float* __restrict__ b_rel,   // [64]
                  const float* __restrict__ w_root)  // [64,64]
{
    __shared__ __align__(16) float smem[SA_FLOATS + SB_FLOATS];  // 33 KB, reused in epilogue
    __shared__ float sbias[HIDDEN];
    __shared__ float scnt[NUM_GRAPHS];
    __shared__ int s_g0, s_span;

    float* sA = smem;               // [64 k][68 nodes] transposed tile
    float* sB = smem + SA_FLOATS;   // [64 k][64 cols]

    const int t  = threadIdx.x;
    const int tx = t & 15;          // col group (4 cols)
    const int ty = t >> 4;          // node group (4 nodes)
    const int base = blockIdx.x * TM;

    if (t < HIDDEN) sbias[t] = b_rel[t];

    float acc[4][4];
    #pragma unroll
    for (int i = 0; i < 4; i++)
        #pragma unroll
        for (int c = 0; c < 4; c++) acc[i][c] = 0.f;

    #pragma unroll
    for (int stage = 0; stage < 2; stage++) {
        const float* A = stage ? g_h1 : g_agg2;
        const float* W = stage ? w_root : w_rel;

        // load A tile transposed: sA[k][m] = A[(base+m)*64 + k]
        #pragma unroll
        for (int r = 0; r < 16; r++) {
            int idx = r * 256 + t;          // 4096 elems
            int m = idx >> 6, k = idx & 63;
            int node = base + m;
            sA[k * SA_STRIDE + m] = (node < N_NODES) ? A[node * HIDDEN + k] : 0.f;
        }
        // load W tile: sB[k][j]
        #pragma unroll
        for (int r = 0; r < 16; r++) {
            int idx = r * 256 + t;
            sB[idx] = W[idx];
        }
        __syncthreads();

        #pragma unroll 8
        for (int k = 0; k < 64; k++) {
            float4 a = *reinterpret_cast<const float4*>(&sA[k * SA_STRIDE + ty * 4]);
            float4 b = *reinterpret_cast<const float4*>(&sB[k * HIDDEN + tx * 4]);
            float av[4] = {a.x, a.y, a.z, a.w};
            float bv[4] = {b.x, b.y, b.z, b.w};
            #pragma unroll
            for (int i = 0; i < 4; i++)
                #pragma unroll
                for (int c = 0; c < 4; c++)
                    acc[i][c] += av[i] * bv[c];
        }
        __syncthreads();
    }

    // bias + relu
    #pragma unroll
    for (int i = 0; i < 4; i++)
        #pragma unroll
        for (int c = 0; c < 4; c++)
            acc[i][c] = fmaxf(acc[i][c] + sbias[tx * 4 + c], 0.f);

    // ---- pooling: smem pre-aggregation (batch is sorted) ----
    if (t == 0) {
        int g0 = batch[base];
        int last = base + TM - 1; if (last >= N_NODES) last = N_NODES - 1;
        int g1 = batch[last];
        s_g0 = g0;
        s_span = g1 - g0 + 1;
    }
    __syncthreads();
    const int g0 = s_g0, span = s_span;

    float* s_pool = smem;   // reuse: span*64 <= 8192 <= SA_FLOATS+SB_FLOATS
    for (int idx = t; idx < span * HIDDEN; idx += 256) s_pool[idx] = 0.f;
    for (int idx = t; idx < span; idx += 256) scnt[idx] = 0.f;
    __syncthreads();

    #pragma unroll
    for (int i = 0; i < 4; i++) {
        int node = base + ty * 4 + i;
        if (node < N_NODES) {
            int g = batch[node] - g0;
            #pragma unroll
            for (int c = 0; c < 4; c++)
                atomicAdd(&s_pool[g * HIDDEN + tx * 4 + c], acc[i][c]);
            if (tx == 0) atomicAdd(&scnt[g], 1.f);
        }
    }
    __syncthreads();

    for (int idx = t; idx < span * HIDDEN; idx += 256) {
        float v = s_pool[idx];
        if (v != 0.f) atomicAdd(&g_pool[g0 * HIDDEN + idx], v);
    }
    for (int idx = t; idx < span; idx += 256) {
        float v = scnt[idx];
        if (v != 0.f) atomicAdd(&g_cnt[g0 + idx], v);
    }
}

// -------- K5: final MLP head, one block, thread = graph --------
__global__ void k_head(const float* __restrict__ w_h1,  // [128,64]
                       const float* __restrict__ b_h1,  // [64]
                       const float* __restrict__ w_h2,  // [64,1]
                       const float* __restrict__ b_h2,  // [1]
                       float* __restrict__ out)
{
    __shared__ float sw1[2 * HIDDEN * HIDDEN];  // 32KB
    __shared__ float sb1[HIDDEN];
    __shared__ float sw2[HIDDEN];
    int t = threadIdx.x;
    for (int i = t; i < 2 * HIDDEN * HIDDEN; i += blockDim.x) sw1[i] = w_h1[i];
    if (t < HIDDEN) { sb1[t] = b_h1[t]; sw2[t] = w_h2[t]; }
    __syncthreads();

    int g = t;
    if (g >= NUM_GRAPHS) return;

    float inv = 1.f / fmaxf(g_cnt[g], 1.f);

    float h[HIDDEN];
    #pragma unroll
    for (int j = 0; j < HIDDEN; j++) h[j] = sb1[j];

    for (int i = 0; i < HIDDEN; i++) {
        float p = g_pool[g * HIDDEN + i];
        float gm = p * inv;   // mean part
        float ga = p;         // add part
        #pragma unroll 8
        for (int j = 0; j < HIDDEN; j++) {
            h[j] += gm * sw1[i * HIDDEN + j]
                  + ga * sw1[(HIDDEN + i) * HIDDEN + j];
        }
    }
    float o = b_h2[0];
    #pragma unroll
    for (int j = 0; j < HIDDEN; j++) o += fmaxf(h[j], 0.f) * sw2[j];
    out[g] = o;
}

extern "C" void kernel_launch(void* const* d_in, const int* in_sizes, int n_in,
                              void* d_out, int out_size) {
    const float* x       = (const float*)d_in[0];
    const int*   eidx    = (const int*)d_in[1];   // [2, E]
    const int*   batch   = (const int*)d_in[2];
    const float* w_rel1  = (const float*)d_in[3];
    const float* b_rel1  = (const float*)d_in[4];
    const float* w_root1 = (const float*)d_in[5];
    const float* w_rel2  = (const float*)d_in[6];
    const float* b_rel2  = (const float*)d_in[7];
    const float* w_root2 = (const float*)d_in[8];
    const float* w_h1    = (const float*)d_in[9];
    const float* b_h1    = (const float*)d_in[10];
    const float* w_h2    = (const float*)d_in[11];
    const float* b_h2    = (const float*)d_in[12];
    float* out = (float*)d_out;

    const int* src = eidx;
    const int* dst = eidx + N_EDGES;

    // K0: zero scratch
    {
        int total = N_NODES * HIDDEN;
        k_zero<<<(total + 255) / 256, 256>>>();
    }
    // K1: layer-1 edge scatter
    k_edge1<<<(N_EDGES + 255) / 256, 256>>>(x, src, dst);
    // K2: layer-1 node update
    k_node1<<<(N_NODES + 3) / 4, 256>>>(x, w_rel1, b_rel1, w_root1);
    // K3: layer-2 edge scatter (16 threads/edge)
    {
        long long threads = (long long)N_EDGES * 16;
        k_edge2<<<(int)((threads + 255) / 256), 256>>>(src, dst);
    }
    // K4: layer-2 tiled GEMM + pooling
    k_node2_pool<<<(N_NODES + TM - 1) / TM, 256>>>(batch, w_rel2, b_rel2, w_root2);
    // K5: head
    k_head<<<1, 128>>>(w_h1, b_h1, w_h2, b_h2, out);
}

// round 3
// speedup vs baseline: 1.4680x; 1.0772x over previous
#include <cuda_runtime.h>
#include <cuda_bf16.h>

#define N_NODES   100000
#define N_EDGES   1200000
#define NUM_GRAPHS 128
#define IN_DIM    5
#define HIDDEN    64

#define SCAN_B    1024
#define N_SCANBLK ((N_NODES + SCAN_B - 1) / SCAN_B)   // 98

// -------- scratch (device globals; no allocations allowed) --------
__device__ __align__(16) float g_h1  [N_NODES * HIDDEN];       // 25.6 MB
__device__ __align__(16) float g_pool[NUM_GRAPHS * HIDDEN];
__device__              float g_cnt [NUM_GRAPHS];
__device__ int   g_deg   [N_NODES];
__device__ int   g_incl  [N_SCANBLK * SCAN_B];   // inclusive scan tmp
__device__ int   g_bsum  [N_SCANBLK];
__device__ int   g_bsumex[N_SCANBLK];
__device__ int   g_rowptr[N_NODES + 1];
__device__ int   g_cursor[N_NODES];
__device__ int   g_csr   [N_EDGES];

// -------- K0: init (zero deg / pool / cnt) --------
__global__ void k_init() {
    int i = blockIdx.x * blockDim.x + threadIdx.x;
    if (i < N_NODES) g_deg[i] = 0;
    if (i < NUM_GRAPHS * HIDDEN) g_pool[i] = 0.f;
    if (i < NUM_GRAPHS) g_cnt[i] = 0.f;
}

// -------- K1: degree histogram by dst --------
__global__ void k_count(const int* __restrict__ dst) {
    int e = blockIdx.x * blockDim.x + threadIdx.x;
    if (e < N_EDGES) atomicAdd(&g_deg[dst[e]], 1);
}

// -------- K2a: per-block inclusive scan --------
__global__ void k_scan1() {
    __shared__ int ss[SCAN_B];
    int t = threadIdx.x;
    int i = blockIdx.x * SCAN_B + t;
    int v = (i < N_NODES) ? g_deg[i] : 0;
    ss[t] = v;
    __syncthreads();
    #pragma unroll
    for (int off = 1; off < SCAN_B; off <<= 1) {
        int u = (t >= off) ? ss[t - off] : 0;
        __syncthreads();
        ss[t] += u;
        __syncthreads();
    }
    g_incl[i] = ss[t];
    if (t == SCAN_B - 1) g_bsum[blockIdx.x] = ss[t];
}

// -------- K2b: scan of block sums (tiny, thread 0) --------
__global__ void k_scan2() {
    if (threadIdx.x == 0) {
        int acc = 0;
        for (int b = 0; b < N_SCANBLK; b++) {
            g_bsumex[b] = acc;
            acc += g_bsum[b];
        }
    }
}

// -------- K2c: finalize row_ptr + cursor; also graph node counts --------
__global__ void k_scan3(const int* __restrict__ batch) {
    int i = blockIdx.x * blockDim.x + threadIdx.x;
    if (i >= N_NODES) return;
    int rp = g_incl[i] - g_deg[i] + g_bsumex[i >> 10];   // exclusive
    g_rowptr[i] = rp;
    g_cursor[i] = rp;
    if (i == 0) g_rowptr[N_NODES] = N_EDGES;
    atomicAdd(&g_cnt[batch[i]], 1.f);
}

// -------- K3: fill CSR (src list grouped by dst) --------
__global__ void k_fill(const int* __restrict__ src, const int* __restrict__ dst) {
    int e = blockIdx.x * blockDim.x + threadIdx.x;
    if (e >= N_EDGES) return;
    int pos = atomicAdd(&g_cursor[dst[e]], 1);
    g_csr[pos] = src[e];
}

// -------- K4: fused layer-1: gather x[src] + GraphConv + relu -> h1 --------
// 256 nodes per block. Phase A: thread-per-node gather (IN_DIM=5).
// Phase B: 16384 outputs / 256 threads.
__global__ __launch_bounds__(256)
void k_layer1(const float* __restrict__ x,
              const float* __restrict__ w_rel,   // [5,64]
              const float* __restrict__ b_rel,
              const float* __restrict__ w_root)  // [5,64]
{
    __shared__ float swr[IN_DIM * HIDDEN];
    __shared__ float swo[IN_DIM * HIDDEN];
    __shared__ float sb[HIDDEN];
    __shared__ float sagg[256][IN_DIM];
    __shared__ float sx  [256][IN_DIM];

    const int t = threadIdx.x;
    const int base = blockIdx.x * 256;

    for (int i = t; i < IN_DIM * HIDDEN; i += 256) { swr[i] = w_rel[i]; swo[i] = w_root[i]; }
    if (t < HIDDEN) sb[t] = b_rel[t];

    // Phase A: gather
    {
        int n = base + t;
        float a0=0,a1=0,a2=0,a3=0,a4=0;
        float x0=0,x1=0,x2=0,x3=0,x4=0;
        if (n < N_NODES) {
            const float* xr = x + (long long)n * IN_DIM;
            x0=xr[0]; x1=xr[1]; x2=xr[2]; x3=xr[3]; x4=xr[4];
            int rb = g_rowptr[n], re = g_rowptr[n + 1];
            for (int i = rb; i < re; i++) {
                const float* sr = x + (long long)g_csr[i] * IN_DIM;
                a0+=sr[0]; a1+=sr[1]; a2+=sr[2]; a3+=sr[3]; a4+=sr[4];
            }
        }
        sagg[t][0]=a0; sagg[t][1]=a1; sagg[t][2]=a2; sagg[t][3]=a3; sagg[t][4]=a4;
        sx[t][0]=x0; sx[t][1]=x1; sx[t][2]=x2; sx[t][3]=x3; sx[t][4]=x4;
    }
    __syncthreads();

    // Phase B: h1 = relu(agg@Wr + b + x@Wroot)
    #pragma unroll 4
    for (int i = 0; i < 64; i++) {
        int idx = i * 256 + t;                 // 0..16383
        int nl = idx >> 6, j = idx & 63;
        int node = base + nl;
        if (node >= N_NODES) break;
        float acc = sb[j];
        #pragma unroll
        for (int k = 0; k < IN_DIM; k++)
            acc += sagg[nl][k] * swr[k * HIDDEN + j] + sx[nl][k] * swo[k * HIDDEN + j];
        g_h1[(long long)base * HIDDEN + idx] = fmaxf(acc, 0.f);
    }
}

// -------- K5: fused layer-2: gather h1 + GraphConv + relu + pooling --------
#define TM 64
#define SA_STRIDE 68
#define SA_FLOATS (64 * SA_STRIDE)
#define SB_FLOATS (64 * HIDDEN)

__global__ __launch_bounds__(256, 3)
void k_layer2(const int* __restrict__ batch,
              const float* __restrict__ w_rel,   // [64,64]
              const float* __restrict__ b_rel,
              const float* __restrict__ w_root)  // [64,64]
{
    __shared__ __align__(16) float sA[SA_FLOATS];   // 17.4 KB
    __shared__ __align__(16) float sB[SB_FLOATS];   // 16 KB (also reused as C tile)
    __shared__ float sbias[HIDDEN];
    __shared__ int   sbatch[TM];

    const int t    = threadIdx.x;
    const int lane = t & 31, wid = t >> 5;
    const int half = lane >> 4, li = lane & 15;
    const int tx   = t & 15, ty = t >> 4;
    const int base = blockIdx.x * TM;
    const int mmax = min(TM, N_NODES - base);

    if (t < HIDDEN) sbias[t] = b_rel[t];
    if (t < TM) sbatch[t] = (base + t < N_NODES) ? batch[base + t] : -1;

    // load W_rel tile
    #pragma unroll
    for (int r = 0; r < 16; r++) sB[r * 256 + t] = w_rel[r * 256 + t];

    // Phase A: warp-per-node gather of h1[src] into sA (transposed)
    #pragma unroll 1
    for (int p = 0; p < 8; p++) {
        int m = p * 8 + wid;
        int n = base + m;
        float a0=0,a1=0,a2=0,a3=0;
        if (n < N_NODES) {
            int rb = g_rowptr[n], re = g_rowptr[n + 1];
            for (int i = rb + half; i < re; i += 2) {
                int s = g_csr[i];
                float4 v = *reinterpret_cast<const float4*>(&g_h1[(long long)s * HIDDEN + li * 4]);
                a0 += v.x; a1 += v.y; a2 += v.z; a3 += v.w;
            }
        }
        a0 += __shfl_down_sync(0xFFFFFFFFu, a0, 16);
        a1 += __shfl_down_sync(0xFFFFFFFFu, a1, 16);
        a2 += __shfl_down_sync(0xFFFFFFFFu, a2, 16);
        a3 += __shfl_down_sync(0xFFFFFFFFu, a3, 16);
        if (half == 0) {
            int k = li * 4;
            sA[(k+0) * SA_STRIDE + m] = a0;
            sA[(k+1) * SA_STRIDE + m] = a1;
            sA[(k+2) * SA_STRIDE + m] = a2;
            sA[(k+3) * SA_STRIDE + m] = a3;
        }
    }
    __syncthreads();

    float acc[4][4];
    #pragma unroll
    for (int i = 0; i < 4; i++)
        #pragma unroll
        for (int c = 0; c < 4; c++) acc[i][c] = 0.f;

    // GEMM stage 0: agg @ W_rel
    #pragma unroll 8
    for (int k = 0; k < 64; k++) {
        float4 a = *reinterpret_cast<const float4*>(&sA[k * SA_STRIDE + ty * 4]);
        float4 b = *reinterpret_cast<const float4*>(&sB[k * HIDDEN + tx * 4]);
        float av[4] = {a.x, a.y, a.z, a.w};
        float bv[4] = {b.x, b.y, b.z, b.w};
        #pragma unroll
        for (int i = 0; i < 4; i++)
            #pragma unroll
            for (int c = 0; c < 4; c++) acc[i][c] += av[i] * bv[c];
    }
    __syncthreads();

    // reload: sA = h1 tile (transposed), sB = W_root
    #pragma unroll
    for (int r = 0; r < 16; r++) {
        int idx = r * 256 + t;
        int m = idx >> 6, k = idx & 63;
        int node = base + m;
        sA[k * SA_STRIDE + m] = (node < N_NODES) ? g_h1[(long long)node * HIDDEN + k] : 0.f;
        sB[idx] = w_root[idx];
    }
    __syncthreads();

    // GEMM stage 1: h1 @ W_root
    #pragma unroll 8
    for (int k = 0; k < 64; k++) {
        float4 a = *reinterpret_cast<const float4*>(&sA[k * SA_STRIDE + ty * 4]);
        float4 b = *reinterpret_cast<const float4*>(&sB[k * HIDDEN + tx * 4]);
        float av[4] = {a.x, a.y, a.z, a.w};
        float bv[4] = {b.x, b.y, b.z, b.w};
        #pragma unroll
        for (int i = 0; i < 4; i++)
            #pragma unroll
            for (int c = 0; c < 4; c++) acc[i][c] += av[i] * bv[c];
    }
    __syncthreads();

    // bias + relu, store C tile into sB (16 KB)
    #pragma unroll
    for (int i = 0; i < 4; i++) {
        float4 v;
        v.x = fmaxf(acc[i][0] + sbias[tx * 4 + 0], 0.f);
        v.y = fmaxf(acc[i][1] + sbias[tx * 4 + 1], 0.f);
        v.z = fmaxf(acc[i][2] + sbias[tx * 4 + 2], 0.f);
        v.w = fmaxf(acc[i][3] + sbias[tx * 4 + 3], 0.f);
        *reinterpret_cast<float4*>(&sB[(ty * 4 + i) * HIDDEN + tx * 4]) = v;
    }
    __syncthreads();

    // Pooling: batch is sorted; thread j accumulates its column, flushing on
    // graph change (span per 64-node tile is ~1-2 graphs).
    if (t < HIDDEN) {
        int j = t;
        int gc = sbatch[0];
        float sum = 0.f;
        for (int m = 0; m < mmax; m++) {
            int g = sbatch[m];
            if (g != gc) {
                atomicAdd(&g_pool[gc * HIDDEN + j], sum);
                gc = g; sum = 0.f;
            }
            sum += sB[m * HIDDEN + j];
        }
        atomicAdd(&g_pool[gc * HIDDEN + j], sum);
    }
}

// -------- K6: final MLP head --------
__global__ void k_head(const float* __restrict__ w_h1,  // [128,64]
                       const float* __restrict__ b_h1,
                       const float* __restrict__ w_h2,  // [64,1]
                       const float* __restrict__ b_h2,
                       float* __restrict__ out)
{
    __shared__ float sw1[2 * HIDDEN * HIDDEN];
    __shared__ float sb1[HIDDEN];
    __shared__ float sw2[HIDDEN];
    int t = threadIdx.x;
    for (int i = t; i < 2 * HIDDEN * HIDDEN; i += blockDim.x) sw1[i] = w_h1[i];
    if (t < HIDDEN) { sb1[t] = b_h1[t]; sw2[t] = w_h2[t]; }
    __syncthreads();

    int g = t;
    if (g >= NUM_GRAPHS) return;

    float inv = 1.f / fmaxf(g_cnt[g], 1.f);
    float h[HIDDEN];
    #pragma unroll
    for (int j = 0; j < HIDDEN; j++) h[j] = sb1[j];

    for (int i = 0; i < HIDDEN; i++) {
        float p = g_pool[g * HIDDEN + i];
        float gm = p * inv;
        #pragma unroll 8
        for (int j = 0; j < HIDDEN; j++)
            h[j] += gm * sw1[i * HIDDEN + j] + p * sw1[(HIDDEN + i) * HIDDEN + j];
    }
    float o = b_h2[0];
    #pragma unroll
    for (int j = 0; j < HIDDEN; j++) o += fmaxf(h[j], 0.f) * sw2[j];
    out[g] = o;
}

extern "C" void kernel_launch(void* const* d_in, const int* in_sizes, int n_in,
                              void* d_out, int out_size) {
    const float* x       = (const float*)d_in[0];
    const int*   eidx    = (const int*)d_in[1];
    const int*   batch   = (const int*)d_in[2];
    const float* w_rel1  = (const float*)d_in[3];
    const float* b_rel1  = (const float*)d_in[4];
    const float* w_root1 = (const float*)d_in[5];
    const float* w_rel2  = (const float*)d_in[6];
    const float* b_rel2  = (const float*)d_in[7];
    const float* w_root2 = (const float*)d_in[8];
    const float* w_h1    = (const float*)d_in[9];
    const float* b_h1    = (const float*)d_in[10];
    const float* w_h2    = (const float*)d_in[11];
    const float* b_h2    = (const float*)d_in[12];
    float* out = (float*)d_out;

    const int* src = eidx;
    const int* dst = eidx + N_EDGES;

    k_init <<<(N_NODES + 255) / 256, 256>>>();
    k_count<<<(N_EDGES + 255) / 256, 256>>>(dst);
    k_scan1<<<N_SCANBLK, SCAN_B>>>();
    k_scan2<<<1, 32>>>();
    k_scan3<<<(N_NODES + 255) / 256, 256>>>(batch);
    k_fill <<<(N_EDGES + 255) / 256, 256>>>(src, dst);

    k_layer1<<<(N_NODES + 255) / 256, 256>>>(x, w_rel1, b_rel1, w_root1);
    k_layer2<<<(N_NODES + TM - 1) / TM, 256>>>(batch, w_rel2, b_rel2, w_root2);
    k_head  <<<1, 128>>>(w_h1, b_h1, w_h2, b_h2, out);
}

// round 4
// speedup vs baseline: 1.7643x; 1.2018x over previous
#include <cuda_runtime.h>
#include <cuda_bf16.h>

#define N_NODES   100000
#define N_EDGES   1200000
#define NUM_GRAPHS 128
#define IN_DIM    5
#define HIDDEN    64

#define SCAN_B    1024
#define N_SCANBLK ((N_NODES + SCAN_B - 1) / SCAN_B)   // 98

// -------- scratch (device globals; zero at module load; each replay leaves
//          them in the same state it found them) --------
__device__ __align__(16) float g_h1  [N_NODES * HIDDEN];   // 25.6 MB
__device__ __align__(16) float g_pool[NUM_GRAPHS * HIDDEN]; // zeroed by k_head post-read
__device__              float g_cnt [NUM_GRAPHS];           // boundary-written (empty graphs stay 0)
__device__ int   g_deg   [N_NODES];                          // zeroed by k_scan23 post-read
__device__ int   g_incl  [N_SCANBLK * SCAN_B];
__device__ int   g_bsum  [N_SCANBLK];
__device__ int   g_gstart[NUM_GRAPHS];
__device__ int   g_rowptr[N_NODES + 1];
__device__ int   g_cursor[N_NODES];
__device__ int   g_csr   [N_EDGES];

// -------- K1: degree histogram by dst (int4 vectorized) --------
__global__ void k_count(const int* __restrict__ dst) {
    int e4 = blockIdx.x * blockDim.x + threadIdx.x;
    if (e4 >= N_EDGES / 4) return;
    int4 d = reinterpret_cast<const int4*>(dst)[e4];
    atomicAdd(&g_deg[d.x], 1);
    atomicAdd(&g_deg[d.y], 1);
    atomicAdd(&g_deg[d.z], 1);
    atomicAdd(&g_deg[d.w], 1);
}

// -------- K2a: per-block inclusive scan (warp-shuffle hierarchical) +
//          graph start boundaries (batch is sorted) --------
__global__ __launch_bounds__(SCAN_B)
void k_scan1(const int* __restrict__ batch) {
    __shared__ int swsum[32];
    const int t = threadIdx.x;
    const int lane = t & 31, w = t >> 5;
    const int i = blockIdx.x * SCAN_B + t;

    int d = (i < N_NODES) ? g_deg[i] : 0;
    int v = d;
    #pragma unroll
    for (int off = 1; off < 32; off <<= 1) {
        int u = __shfl_up_sync(0xFFFFFFFFu, v, off);
        if (lane >= off) v += u;
    }
    if (lane == 31) swsum[w] = v;
    __syncthreads();
    if (w == 0) {
        int s = swsum[lane];
        #pragma unroll
        for (int off = 1; off < 32; off <<= 1) {
            int u = __shfl_up_sync(0xFFFFFFFFu, s, off);
            if (lane >= off) s += u;
        }
        swsum[lane] = s;
    }
    __syncthreads();
    int incl = v + (w ? swsum[w - 1] : 0);
    g_incl[blockIdx.x * SCAN_B + t] = incl;
    if (t == SCAN_B - 1) g_bsum[blockIdx.x] = incl;

    // graph start boundary (sorted batch): 128 plain stores total
    if (i < N_NODES) {
        int b = batch[i];
        if (i == 0 || batch[i - 1] != b) g_gstart[b] = i;
    }
}

// -------- K2b: finalize rowptr/cursor, zero deg, graph counts --------
// Each block redundantly reduces the 98 block sums (cheap, avoids a kernel).
__global__ __launch_bounds__(SCAN_B)
void k_scan23(const int* __restrict__ batch) {
    __shared__ int sred[32];
    __shared__ int s_bpre;
    const int t = threadIdx.x;
    const int lane = t & 31, w = t >> 5;
    const int bid = blockIdx.x;

    int v = (t < bid) ? g_bsum[t] : 0;      // t < bid <= 97 < 1024
    #pragma unroll
    for (int off = 16; off > 0; off >>= 1) v += __shfl_down_sync(0xFFFFFFFFu, v, off);
    if (lane == 0) sred[w] = v;
    __syncthreads();
    if (w == 0) {
        int s = sred[lane];
        #pragma unroll
        for (int off = 16; off > 0; off >>= 1) s += __shfl_down_sync(0xFFFFFFFFu, s, off);
        if (lane == 0) s_bpre = s;
    }
    __syncthreads();
    const int bpre = s_bpre;

    int i = bid * SCAN_B + t;
    if (i < N_NODES) {
        int d = g_deg[i];
        int rp = g_incl[i] - d + bpre;      // exclusive prefix
        g_rowptr[i] = rp;
        g_cursor[i] = rp;
        g_deg[i] = 0;                        // ready for next replay
        int b = batch[i];
        if (i == N_NODES - 1 || batch[i + 1] != b)
            g_cnt[b] = (float)(i + 1 - g_gstart[b]);   // run length, no atomics
    }
    if (bid == 0 && t == 0) g_rowptr[N_NODES] = N_EDGES;
}

// -------- K3: fill CSR (src grouped by dst), int4 vectorized --------
__global__ void k_fill(const int* __restrict__ src, const int* __restrict__ dst) {
    int e4 = blockIdx.x * blockDim.x + threadIdx.x;
    if (e4 >= N_EDGES / 4) return;
    int4 s = reinterpret_cast<const int4*>(src)[e4];
    int4 d = reinterpret_cast<const int4*>(dst)[e4];
    g_csr[atomicAdd(&g_cursor[d.x], 1)] = s.x;
    g_csr[atomicAdd(&g_cursor[d.y], 1)] = s.y;
    g_csr[atomicAdd(&g_cursor[d.z], 1)] = s.z;
    g_csr[atomicAdd(&g_cursor[d.w], 1)] = s.w;
}

// -------- K4: fused layer-1: gather (4 lanes/node) + GraphConv + relu --------
// 64 nodes per 256-thread block.
__global__ __launch_bounds__(256)
void k_layer1(const float* __restrict__ x,
              const float* __restrict__ w_rel,   // [5,64]
              const float* __restrict__ b_rel,
              const float* __restrict__ w_root)  // [5,64]
{
    __shared__ float swr[IN_DIM * HIDDEN];
    __shared__ float swo[IN_DIM * HIDDEN];
    __shared__ float sb[HIDDEN];
    __shared__ float sagg[64][IN_DIM];
    __shared__ float sx  [64][IN_DIM];

    const int t = threadIdx.x;
    const int base = blockIdx.x * 64;

    for (int i = t; i < IN_DIM * HIDDEN; i += 256) { swr[i] = w_rel[i]; swo[i] = w_root[i]; }
    if (t < HIDDEN) sb[t] = b_rel[t];

    // Phase A: 4 lanes per node
    {
        const int nl = t >> 2, l = t & 3;
        const int n = base + nl;
        float a0=0,a1=0,a2=0,a3=0,a4=0;
        if (n < N_NODES) {
            int rb = g_rowptr[n], re = g_rowptr[n + 1];
            for (int i = rb + l; i < re; i += 4) {
                const float* sr = x + (long long)g_csr[i] * IN_DIM;
                a0 += sr[0]; a1 += sr[1]; a2 += sr[2]; a3 += sr[3]; a4 += sr[4];
            }
        }
        #pragma unroll
        for (int off = 1; off <= 2; off <<= 1) {
            a0 += __shfl_xor_sync(0xFFFFFFFFu, a0, off);
            a1 += __shfl_xor_sync(0xFFFFFFFFu, a1, off);
            a2 += __shfl_xor_sync(0xFFFFFFFFu, a2, off);
            a3 += __shfl_xor_sync(0xFFFFFFFFu, a3, off);
            a4 += __shfl_xor_sync(0xFFFFFFFFu, a4, off);
        }
        if (l == 0 && n < N_NODES) {
            sagg[nl][0]=a0; sagg[nl][1]=a1; sagg[nl][2]=a2; sagg[nl][3]=a3; sagg[nl][4]=a4;
            const float* xr = x + (long long)n * IN_DIM;
            sx[nl][0]=xr[0]; sx[nl][1]=xr[1]; sx[nl][2]=xr[2]; sx[nl][3]=xr[3]; sx[nl][4]=xr[4];
        }
    }
    __syncthreads();

    // Phase B: 64x64 outputs over 16 iterations
    #pragma unroll 4
    for (int it = 0; it < 16; it++) {
        int idx = it * 256 + t;
        int nl = idx >> 6, j = idx & 63;
        int node = base + nl;
        if (node >= N_NODES) break;
        float acc = sb[j];
        #pragma unroll
        for (int k = 0; k < IN_DIM; k++)
            acc += sagg[nl][k] * swr[k * HIDDEN + j] + sx[nl][k] * swo[k * HIDDEN + j];
        g_h1[(long long)node * HIDDEN + j] = fmaxf(acc, 0.f);
    }
}

// -------- K5: fused layer-2: gather h1 + GraphConv + relu + pooling --------
#define TM 64
#define SA_STRIDE 68
#define SA_FLOATS (64 * SA_STRIDE)
#define SB_FLOATS (64 * HIDDEN)

__global__ __launch_bounds__(256, 4)
void k_layer2(const int* __restrict__ batch,
              const float* __restrict__ w_rel,   // [64,64]
              const float* __restrict__ b_rel,
              const float* __restrict__ w_root)  // [64,64]
{
    __shared__ __align__(16) float sA[SA_FLOATS];
    __shared__ __align__(16) float sB[SB_FLOATS];
    __shared__ float sbias[HIDDEN];
    __shared__ int   sbatch[TM];

    const int t    = threadIdx.x;
    const int lane = t & 31, wid = t >> 5;
    const int half = lane >> 4, li = lane & 15;
    const int tx   = t & 15, ty = t >> 4;
    const int base = blockIdx.x * TM;
    const int mmax = min(TM, N_NODES - base);

    if (t < HIDDEN) sbias[t] = b_rel[t];
    if (t < TM) sbatch[t] = (base + t < N_NODES) ? batch[base + t] : -1;

    #pragma unroll
    for (int r = 0; r < 16; r++) sB[r * 256 + t] = w_rel[r * 256 + t];

    // Phase A: warp-per-node gather into sA (transposed)
    #pragma unroll 1
    for (int p = 0; p < 8; p++) {
        int m = p * 8 + wid;
        int n = base + m;
        float a0=0,a1=0,a2=0,a3=0;
        if (n < N_NODES) {
            int rb = g_rowptr[n], re = g_rowptr[n + 1];
            for (int i = rb + half; i < re; i += 2) {
                int s = g_csr[i];
                float4 v = *reinterpret_cast<const float4*>(&g_h1[(long long)s * HIDDEN + li * 4]);
                a0 += v.x; a1 += v.y; a2 += v.z; a3 += v.w;
            }
        }
        a0 += __shfl_down_sync(0xFFFFFFFFu, a0, 16);
        a1 += __shfl_down_sync(0xFFFFFFFFu, a1, 16);
        a2 += __shfl_down_sync(0xFFFFFFFFu, a2, 16);
        a3 += __shfl_down_sync(0xFFFFFFFFu, a3, 16);
        if (half == 0) {
            int k = li * 4;
            sA[(k+0) * SA_STRIDE + m] = a0;
            sA[(k+1) * SA_STRIDE + m] = a1;
            sA[(k+2) * SA_STRIDE + m] = a2;
            sA[(k+3) * SA_STRIDE + m] = a3;
        }
    }
    __syncthreads();

    float acc[4][4];
    #pragma unroll
    for (int i = 0; i < 4; i++)
        #pragma unroll
        for (int c = 0; c < 4; c++) acc[i][c] = 0.f;

    // GEMM stage 0: agg @ W_rel
    #pragma unroll 8
    for (int k = 0; k < 64; k++) {
        float4 a = *reinterpret_cast<const float4*>(&sA[k * SA_STRIDE + ty * 4]);
        float4 b = *reinterpret_cast<const float4*>(&sB[k * HIDDEN + tx * 4]);
        float av[4] = {a.x, a.y, a.z, a.w};
        float bv[4] = {b.x, b.y, b.z, b.w};
        #pragma unroll
        for (int i = 0; i < 4; i++)
            #pragma unroll
            for (int c = 0; c < 4; c++) acc[i][c] += av[i] * bv[c];
    }
    __syncthreads();

    // reload: sA = h1 tile (transposed), sB = W_root
    #pragma unroll
    for (int r = 0; r < 16; r++) {
        int idx = r * 256 + t;
        int m = idx >> 6, k = idx & 63;
        int node = base + m;
        sA[k * SA_STRIDE + m] = (node < N_NODES) ? g_h1[(long long)node * HIDDEN + k] : 0.f;
        sB[idx] = w_root[idx];
    }
    __syncthreads();

    // GEMM stage 1: h1 @ W_root
    #pragma unroll 8
    for (int k = 0; k < 64; k++) {
        float4 a = *reinterpret_cast<const float4*>(&sA[k * SA_STRIDE + ty * 4]);
        float4 b = *reinterpret_cast<const float4*>(&sB[k * HIDDEN + tx * 4]);
        float av[4] = {a.x, a.y, a.z, a.w};
        float bv[4] = {b.x, b.y, b.z, b.w};
        #pragma unroll
        for (int i = 0; i < 4; i++)
            #pragma unroll
            for (int c = 0; c < 4; c++) acc[i][c] += av[i] * bv[c];
    }
    __syncthreads();

    // bias + relu, stage C tile in sB
    #pragma unroll
    for (int i = 0; i < 4; i++) {
        float4 v;
        v.x = fmaxf(acc[i][0] + sbias[tx * 4 + 0], 0.f);
        v.y = fmaxf(acc[i][1] + sbias[tx * 4 + 1], 0.f);
        v.z = fmaxf(acc[i][2] + sbias[tx * 4 + 2], 0.f);
        v.w = fmaxf(acc[i][3] + sbias[tx * 4 + 3], 0.f);
        *reinterpret_cast<float4*>(&sB[(ty * 4 + i) * HIDDEN + tx * 4]) = v;
    }
    __syncthreads();

    // Pooling: sorted batch, run-length flush per column
    if (t < HIDDEN) {
        int j = t;
        int gc = sbatch[0];
        float sum = 0.f;
        for (int m = 0; m < mmax; m++) {
            int g = sbatch[m];
            if (g != gc) {
                atomicAdd(&g_pool[gc * HIDDEN + j], sum);
                gc = g; sum = 0.f;
            }
            sum += sB[m * HIDDEN + j];
        }
        atomicAdd(&g_pool[gc * HIDDEN + j], sum);
    }
}

// -------- K6: final MLP head; zeroes g_pool after consuming it --------
__global__ void k_head(const float* __restrict__ w_h1,  // [128,64]
                       const float* __restrict__ b_h1,
                       const float* __restrict__ w_h2,  // [64,1]
                       const float* __restrict__ b_h2,
                       float* __restrict__ out)
{
    __shared__ float sw1[2 * HIDDEN * HIDDEN];
    __shared__ float sb1[HIDDEN];
    __shared__ float sw2[HIDDEN];
    int t = threadIdx.x;
    for (int i = t; i < 2 * HIDDEN * HIDDEN; i += blockDim.x) sw1[i] = w_h1[i];
    if (t < HIDDEN) { sb1[t] = b_h1[t]; sw2[t] = w_h2[t]; }
    __syncthreads();

    int g = t;
    if (g >= NUM_GRAPHS) return;

    float inv = 1.f / fmaxf(g_cnt[g], 1.f);
    float h[HIDDEN];
    #pragma unroll
    for (int j = 0; j < HIDDEN; j++) h[j] = sb1[j];

    for (int i = 0; i < HIDDEN; i++) {
        float p = g_pool[g * HIDDEN + i];
        float gm = p * inv;
        #pragma unroll 8
        for (int j = 0; j < HIDDEN; j++)
            h[j] += gm * sw1[i * HIDDEN + j] + p * sw1[(HIDDEN + i) * HIDDEN + j];
    }
    float o = b_h2[0];
    #pragma unroll
    for (int j = 0; j < HIDDEN; j++) o += fmaxf(h[j], 0.f) * sw2[j];
    out[g] = o;

    // leave pool zeroed for the next replay (only this thread read row g)
    #pragma unroll
    for (int i = 0; i < HIDDEN; i++) g_pool[g * HIDDEN + i] = 0.f;
}

extern "C" void kernel_launch(void* const* d_in, const int* in_sizes, int n_in,
                              void* d_out, int out_size) {
    const float* x       = (const float*)d_in[0];
    const int*   eidx    = (const int*)d_in[1];
    const int*   batch   = (const int*)d_in[2];
    const float* w_rel1  = (const float*)d_in[3];
    const float* b_rel1  = (const float*)d_in[4];
    const float* w_root1 = (const float*)d_in[5];
    const float* w_rel2  = (const float*)d_in[6];
    const float* b_rel2  = (const float*)d_in[7];
    const float* w_root2 = (const float*)d_in[8];
    const float* w_h1    = (const float*)d_in[9];
    const float* b_h1    = (const float*)d_in[10];
    const float* w_h2    = (const float*)d_in[11];
    const float* b_h2    = (const float*)d_in[12];
    float* out = (float*)d_out;

    const int* src = eidx;
    const int* dst = eidx + N_EDGES;

    k_count <<<(N_EDGES / 4 + 255) / 256, 256>>>(dst);
    k_scan1 <<<N_SCANBLK, SCAN_B>>>(batch);
    k_scan23<<<N_SCANBLK, SCAN_B>>>(batch);
    k_fill  <<<(N_EDGES / 4 + 255) / 256, 256>>>(src, dst);
    k_layer1<<<(N_NODES + 63) / 64, 256>>>(x, w_rel1, b_rel1, w_root1);
    k_layer2<<<(N_NODES + TM - 1) / TM, 256>>>(batch, w_rel2, b_rel2, w_root2);
    k_head  <<<1, 128>>>(w_h1, b_h1, w_h2, b_h2, out);
}